// round 9
// baseline (speedup 1.0000x reference)
#include <cuda_runtime.h>
#include <math.h>

#define T_LEN 480000
#define B_ROWS 64

// RN(1/16000): matches XLA's divide->multiply-by-reciprocal rewrite.
// Load-bearing for correctness (round-4 win) -- do not change.
#define INV_SR 6.25e-5f

// ---------------------------------------------------------------------------
// Fast accurate sine, take 2. Round-8 failure: deg-11 Taylor poly on [-pi,pi]
// has 4.6e-4 edge error (pi^13/13!). Fix: reduce mod PI (not 2pi) so the SAME
// poly runs on [-pi/2, pi/2] where truncation is (pi/2)^13/13! ~ 5.7e-8.
// Sign = parity of n, applied by XOR (magic-number trick leaves integer n in
// the low mantissa bits of jf). ~13 instr: no cos core, no selects.
// Valid here: 0 <= x <= 424 -> n <= 135 (Cody-Waite products exact in FMA).
// All explicit _rn intrinsics: fast-math-immune.
// ---------------------------------------------------------------------------
__device__ __forceinline__ float sin_fast(float x)
{
    const float MAGIC = 12582912.0f;                   // 1.5 * 2^23
    float jf = __fmaf_rn(x, 0.31830988618379067154f, MAGIC);  // round(x/pi)
    int   q  = __float_as_int(jf);                     // low bits = n
    float n  = __fsub_rn(jf, MAGIC);

    // r = x - n*pi, 2-term Cody-Waite (pi_hi = f32(pi) = 0x40490FDB)
    float r = __fmaf_rn(n, -3.14159274101257324219f, x);
    r = __fmaf_rn(n, 8.74227765734758577e-8f, r);      // +n*(pi_hi - pi)

    float s2 = __fmul_rn(r, r);
    float p = __fmaf_rn(-2.3889859e-08f, s2, 2.7525562e-06f);
    p = __fmaf_rn(p, s2, -1.9840874e-04f);
    p = __fmaf_rn(p, s2,  8.3333310e-03f);
    p = __fmaf_rn(p, s2, -1.6666667e-01f);
    float sr = __fmaf_rn(__fmul_rn(p, s2), r, r);

    // sin(x) = (-1)^n * sin(r): flip sign bit when n is odd.
    return __int_as_float(__float_as_int(sr) ^ (q << 31));
}

// One (i,b) sample. CHECK=false: i >= 1024 > 800 >= delay proves rp >= 0 and
// il >= 0; skip the clamp + select.
template<bool CHECK>
__device__ __forceinline__ float chorus_sample(
    const float* __restrict__ row, int i, float posf, float t, float4 p)
{
    // arg = ((2*pi)*rate) * t -- exact reference f32 op order (p.x = 2pi*rate).
    const float arg = __fmul_rn(p.x, t);
    const float lfo = sin_fast(arg);

    // delay = cds + ((lfo*depth)*cds) -- exact ref rounding order, clip [1,800].
    float delay = __fadd_rn(p.z, __fmul_rn(__fmul_rn(lfo, p.y), p.z));
    delay = fminf(fmaxf(delay, 1.0f), 800.0f);

    const float rp = __fsub_rn(posf, delay);           // ref's f32 quantization
    int il = __float2int_rd(rp);
    if (CHECK) il = max(il, 0);
    const float frac = __fsub_rn(rp, floorf(rp));

    const float a0 = __ldg(row + il);
    const float a1 = __ldg(row + il + 1);
    const float x  = __ldg(row + i);

    float delayed = __fmaf_rn(frac, __fsub_rn(a1, a0), a0);
    if (CHECK) delayed = (rp >= 0.0f) ? delayed : 0.0f;

    // x*(1-m) + d*m == x + m*(d-x); ±1ulp direct error, un-amplified.
    return __fmaf_rn(p.w, __fsub_rn(delayed, x), x);
}

template<bool CHECK>
__device__ __forceinline__ void chorus_body(
    const float* __restrict__ audio, float* __restrict__ out,
    const float4* __restrict__ s_p, int i)
{
    const float posf = (float)i;                       // exact (i < 2^24)
    const float t = __fmul_rn(posf, INV_SR);           // XLA reciprocal-mul

    const float* row  = audio;
    float*       orow = out;

    #pragma unroll 8
    for (int b = 0; b < B_ROWS; ++b, row += T_LEN, orow += T_LEN) {
        const float4 p = s_p[b];                       // one LDS.128 broadcast
        orow[i] = chorus_sample<CHECK>(row, i, posf, t, p);
    }
}

__global__ __launch_bounds__(256)
void chorus_kernel(const float* __restrict__ audio,
                   const float* __restrict__ rate_hz,
                   const float* __restrict__ depth,
                   const float* __restrict__ centre_ms,
                   const float* __restrict__ mix,
                   float* __restrict__ out)
{
    __shared__ float4 s_p[B_ROWS];                     // {2pi*rate, depth, cds, mix}

    const float TWO_PI_F = 6.28318530717958647692f;    // f32 = 0x40C90FDB
    if (threadIdx.x < B_ROWS) {
        const int b = threadIdx.x;
        float4 p;
        p.x = __fmul_rn(TWO_PI_F, __ldg(rate_hz + b));
        p.y = __ldg(depth + b);
        p.z = __fmul_rn(__ldg(centre_ms + b), 16.0f);
        p.w = __ldg(mix + b);
        s_p[b] = p;
    }
    __syncthreads();

    const int i = blockIdx.x * blockDim.x + threadIdx.x;
    if (i >= T_LEN) return;

    // Block-uniform specialization: bid >= 4 -> i >= 1024 -> rp, il in range.
    if (blockIdx.x >= 4) chorus_body<false>(audio, out, s_p, i);
    else                 chorus_body<true >(audio, out, s_p, i);
}

extern "C" void kernel_launch(void* const* d_in, const int* in_sizes, int n_in,
                              void* d_out, int out_size)
{
    // metadata order: audio, rate_hz, depth, centre_delay_ms, feedback(unused), mix
    const float* audio     = (const float*)d_in[0];
    const float* rate_hz   = (const float*)d_in[1];
    const float* depth     = (const float*)d_in[2];
    const float* centre_ms = (const float*)d_in[3];
    const float* mix       = (const float*)d_in[5];
    float* out = (float*)d_out;

    (void)in_sizes; (void)n_in; (void)out_size;

    const int threads = 256;
    const int blocks  = (T_LEN + threads - 1) / threads;   // 1875
    chorus_kernel<<<blocks, threads>>>(audio, rate_hz, depth, centre_ms, mix, out);
}

// round 10
// speedup vs baseline: 1.2124x; 1.2124x over previous
#include <cuda_runtime.h>
#include <math.h>

#define T_LEN 480000
#define B_ROWS 64

// RN(1/16000): matches XLA's divide->multiply-by-reciprocal rewrite.
// Load-bearing for correctness (round-4 win) -- do not change.
#define INV_SR 6.25e-5f

// ---------------------------------------------------------------------------
// Fast accurate sine (validated round 9: rel_err 2.17e-4). Reduce mod PI,
// deg-11 odd minimax on [-pi/2, pi/2], sign via parity XOR. ~13 instr.
// All explicit _rn intrinsics: fast-math-immune. BIT-IDENTICAL to round 9.
// ---------------------------------------------------------------------------
__device__ __forceinline__ float sin_fast(float x)
{
    const float MAGIC = 12582912.0f;                   // 1.5 * 2^23
    float jf = __fmaf_rn(x, 0.31830988618379067154f, MAGIC);  // round(x/pi)
    int   q  = __float_as_int(jf);                     // low bits = n
    float n  = __fsub_rn(jf, MAGIC);

    // r = x - n*pi, 2-term Cody-Waite (pi_hi = f32(pi) = 0x40490FDB)
    float r = __fmaf_rn(n, -3.14159274101257324219f, x);
    r = __fmaf_rn(n, 8.74227765734758577e-8f, r);      // +n*(pi_hi - pi)

    float s2 = __fmul_rn(r, r);
    float p = __fmaf_rn(-2.3889859e-08f, s2, 2.7525562e-06f);
    p = __fmaf_rn(p, s2, -1.9840874e-04f);
    p = __fmaf_rn(p, s2,  8.3333310e-03f);
    p = __fmaf_rn(p, s2, -1.6666667e-01f);
    float sr = __fmaf_rn(__fmul_rn(p, s2), r, r);

    // sin(x) = (-1)^n * sin(r): flip sign bit when n is odd.
    return __int_as_float(__float_as_int(sr) ^ (q << 31));
}

// One (i,b) sample. CHECK=false: i >= 1024 > 800 >= delay proves rp >= 0 and
// il >= 0; skip the clamp + select.
template<bool CHECK>
__device__ __forceinline__ float chorus_sample(
    const float* __restrict__ row, int i, float posf, float t, float4 p)
{
    // arg = ((2*pi)*rate) * t -- exact reference f32 op order (p.x = 2pi*rate).
    const float arg = __fmul_rn(p.x, t);
    const float lfo = sin_fast(arg);

    // delay = cds + ((lfo*depth)*cds) -- exact ref rounding order, clip [1,800].
    float delay = __fadd_rn(p.z, __fmul_rn(__fmul_rn(lfo, p.y), p.z));
    delay = fminf(fmaxf(delay, 1.0f), 800.0f);

    const float rp = __fsub_rn(posf, delay);           // ref's f32 quantization
    int il = __float2int_rd(rp);
    if (CHECK) il = max(il, 0);
    const float frac = __fsub_rn(rp, floorf(rp));

    const float a0 = __ldg(row + il);
    const float a1 = __ldg(row + il + 1);
    const float x  = __ldg(row + i);

    float delayed = __fmaf_rn(frac, __fsub_rn(a1, a0), a0);
    if (CHECK) delayed = (rp >= 0.0f) ? delayed : 0.0f;

    // x*(1-m) + d*m == x + m*(d-x); ±1ulp direct error, un-amplified.
    return __fmaf_rn(p.w, __fsub_rn(delayed, x), x);
}

template<bool CHECK>
__device__ __forceinline__ void chorus_body(
    const float* __restrict__ audio, float* __restrict__ out,
    const float4* __restrict__ s_p, int i)
{
    const float posf = (float)i;                       // exact (i < 2^24)
    const float t = __fmul_rn(posf, INV_SR);           // XLA reciprocal-mul

    const float* row  = audio;
    float*       orow = out;

    // unroll 4 (not 8): keeps live ranges short so ptxas meets the 32-reg
    // cap from __launch_bounds__(256, 8) without spilling. Occupancy is the
    // binding resource on this kernel (rounds 6 & 9 post-mortems).
    #pragma unroll 4
    for (int b = 0; b < B_ROWS; ++b, row += T_LEN, orow += T_LEN) {
        const float4 p = s_p[b];                       // one LDS.128 broadcast
        orow[i] = chorus_sample<CHECK>(row, i, posf, t, p);
    }
}

__global__ __launch_bounds__(256, 8)   // force <=32 regs -> 8 blocks/SM
void chorus_kernel(const float* __restrict__ audio,
                   const float* __restrict__ rate_hz,
                   const float* __restrict__ depth,
                   const float* __restrict__ centre_ms,
                   const float* __restrict__ mix,
                   float* __restrict__ out)
{
    __shared__ float4 s_p[B_ROWS];                     // {2pi*rate, depth, cds, mix}

    const float TWO_PI_F = 6.28318530717958647692f;    // f32 = 0x40C90FDB
    if (threadIdx.x < B_ROWS) {
        const int b = threadIdx.x;
        float4 p;
        p.x = __fmul_rn(TWO_PI_F, __ldg(rate_hz + b));
        p.y = __ldg(depth + b);
        p.z = __fmul_rn(__ldg(centre_ms + b), 16.0f);
        p.w = __ldg(mix + b);
        s_p[b] = p;
    }
    __syncthreads();

    const int i = blockIdx.x * blockDim.x + threadIdx.x;
    if (i >= T_LEN) return;

    // Block-uniform specialization: bid >= 4 -> i >= 1024 -> rp, il in range.
    if (blockIdx.x >= 4) chorus_body<false>(audio, out, s_p, i);
    else                 chorus_body<true >(audio, out, s_p, i);
}

extern "C" void kernel_launch(void* const* d_in, const int* in_sizes, int n_in,
                              void* d_out, int out_size)
{
    // metadata order: audio, rate_hz, depth, centre_delay_ms, feedback(unused), mix
    const float* audio     = (const float*)d_in[0];
    const float* rate_hz   = (const float*)d_in[1];
    const float* depth     = (const float*)d_in[2];
    const float* centre_ms = (const float*)d_in[3];
    const float* mix       = (const float*)d_in[5];
    float* out = (float*)d_out;

    (void)in_sizes; (void)n_in; (void)out_size;

    const int threads = 256;
    const int blocks  = (T_LEN + threads - 1) / threads;   // 1875
    chorus_kernel<<<blocks, threads>>>(audio, rate_hz, depth, centre_ms, mix, out);
}